// round 7
// baseline (speedup 1.0000x reference)
#include <cuda_runtime.h>
#include <cuda_bf16.h>

typedef unsigned int u32; typedef unsigned long long u64;
#define Mmol 2048
#define Aat 24
#define Nnode (Mmol*Aat)
#define PIT 272
#define IMG 34816

// EA per (m, task t of 18): 8 ks-chunks of 512 u32: [hi mb0|hi mb1|lo mb0|lo mb1] x 128
__device__ u32   g_EAf[(size_t)Mmol*18*4096];   // 604 MB
__device__ float g_h  [(size_t)Nnode*128];
__device__ float g_x  [(size_t)Nnode*128];
__device__ float g_agg[(size_t)Nnode*128];
__device__ __align__(16) unsigned char g_Wimg[5][2][32768];

__device__ __forceinline__ u32 smaddr(const void* p){
    u32 a; asm("{ .reg .u64 t; cvta.to.shared.u64 t, %1; cvt.u32.u64 %0, t; }" : "=r"(a) : "l"(p)); return a;
}
__device__ __forceinline__ float ssp(float x){
    return fmaxf(x, 0.f) + __logf(1.f + __expf(-fabsf(x))) - 0.6931471805599453f;
}
__device__ __forceinline__ void cpa16(u32 dst, const void* src){
    asm volatile("cp.async.cg.shared.global [%0], [%1], 16;" :: "r"(dst), "l"(src) : "memory");
}
#define CP_COMMIT asm volatile("cp.async.commit_group;" ::: "memory")
#define CP_WAIT0  asm volatile("cp.async.wait_group 0;"  ::: "memory")
__device__ __forceinline__ void ldsm4(u32* r, u32 a){
    asm volatile("ldmatrix.sync.aligned.m8n8.x4.shared.b16 {%0,%1,%2,%3}, [%4];"
        : "=r"(r[0]),"=r"(r[1]),"=r"(r[2]),"=r"(r[3]) : "r"(a));
}
__device__ __forceinline__ void ldsm4t(u32* r, u32 a){
    asm volatile("ldmatrix.sync.aligned.m8n8.x4.trans.shared.b16 {%0,%1,%2,%3}, [%4];"
        : "=r"(r[0]),"=r"(r[1]),"=r"(r[2]),"=r"(r[3]) : "r"(a));
}
__device__ __forceinline__ void mma_bf(float* d, const u32* a, u32 b0, u32 b1){
    asm volatile("mma.sync.aligned.m16n8k16.row.col.f32.bf16.bf16.f32 "
        "{%0,%1,%2,%3}, {%4,%5,%6,%7}, {%8,%9}, {%0,%1,%2,%3};"
        : "+f"(d[0]),"+f"(d[1]),"+f"(d[2]),"+f"(d[3])
        : "r"(a[0]),"r"(a[1]),"r"(a[2]),"r"(a[3]),"r"(b0),"r"(b1));
}
__device__ __forceinline__ void sp2(float x, float y, u32& h, u32& l){
    __nv_bfloat162 hb = __floats2bfloat162_rn(x, y);
    __nv_bfloat162 lb = __floats2bfloat162_rn(x - __bfloat162float(hb.x), y - __bfloat162float(hb.y));
    h = *(u32*)&hb; l = *(u32*)&lb;
}
__device__ __forceinline__ void stage_band(const float* __restrict__ src, char* Ah, char* Al, int R, int lane){
    #pragma unroll 4
    for (int i = 0; i < 16; ++i){
        int row = R + i;
        float4 v = ((const float4*)src)[row*32 + lane];
        u32 h0,l0,h1,l1; sp2(v.x,v.y,h0,l0); sp2(v.z,v.w,h1,l1);
        int o = row*PIT + lane*8;
        *(uint2*)(Ah+o) = make_uint2(h0,h1);
        *(uint2*)(Al+o) = make_uint2(l0,l1);
    }
}
__device__ __forceinline__ void wgemm3(float acc[16][4], u32 baseAh, u32 baseAl,
                                       u32 baseBh, u32 baseBl, int lane){
    u32 off = (lane & 15)*PIT + (lane >> 4)*16;
    #pragma unroll
    for (int ks = 0; ks < 8; ++ks){
        u32 ah[4], al[4];
        ldsm4(ah, baseAh + off + ks*32);
        ldsm4(al, baseAl + off + ks*32);
        #pragma unroll
        for (int nb = 0; nb < 8; ++nb){
            u32 bh[4], bl[4];
            u32 ba = off + ks*(16*PIT) + nb*32;
            ldsm4t(bh, baseBh + ba); ldsm4t(bl, baseBl + ba);
            mma_bf(acc[nb*2],   ah, bh[0], bh[1]);
            mma_bf(acc[nb*2],   ah, bl[0], bl[1]);
            mma_bf(acc[nb*2],   al, bh[0], bh[1]);
            mma_bf(acc[nb*2+1], ah, bh[2], bh[3]);
            mma_bf(acc[nb*2+1], ah, bl[2], bl[3]);
            mma_bf(acc[nb*2+1], al, bh[2], bh[3]);
        }
    }
}
__device__ __forceinline__ void zacc16(float acc[16][4]){
    #pragma unroll
    for (int i=0;i<16;++i){ acc[i][0]=0.f;acc[i][1]=0.f;acc[i][2]=0.f;acc[i][3]=0.f; }
}
__device__ __forceinline__ void write_mid(const float acc[16][4], const float* b1s,
                                          char* Ah, char* Al, int R, int lane){
    int r0 = R + (lane>>2), cb = (lane&3)*2;
    #pragma unroll
    for (int nb = 0; nb < 16; ++nb){
        int c = nb*8 + cb;
        float bx = b1s[c], by = b1s[c+1];
        u32 h0,l0,h1,l1;
        sp2(ssp(acc[nb][0]+bx), ssp(acc[nb][1]+by), h0, l0);
        sp2(ssp(acc[nb][2]+bx), ssp(acc[nb][3]+by), h1, l1);
        *(u32*)(Ah + r0*PIT + c*2) = h0;     *(u32*)(Al + r0*PIT + c*2) = l0;
        *(u32*)(Ah + (r0+8)*PIT + c*2) = h1; *(u32*)(Al + (r0+8)*PIT + c*2) = l1;
    }
}

// merged: weight images (blocks 0-4) + h init (rest)
__global__ void k_init(const int* __restrict__ charges, const float* __restrict__ emb,
                       const float* nlw, const float* ew1, const float* ew2,
                       const float* nw1, const float* nw2){
    if (blockIdx.x < 5){
        if (threadIdx.x >= 128) return;
        const float* srcs[5] = {nlw, ew1, ew2, nw1, nw2};
        const float* src = srcs[blockIdx.x];
        int n = threadIdx.x;
        for (int k = 0; k < 128; ++k){
            float v = src[k*128 + n];
            __nv_bfloat16 h = __float2bfloat16_rn(v);
            __nv_bfloat16 l = __float2bfloat16_rn(v - __bfloat162float(h));
            *(__nv_bfloat16*)(g_Wimg[blockIdx.x][0] + k*256 + n*2) = h;
            *(__nv_bfloat16*)(g_Wimg[blockIdx.x][1] + k*256 + n*2) = l;
        }
        return;
    }
    int idx = (blockIdx.x-5)*256 + threadIdx.x;
    g_h[idx] = emb[charges[idx>>7]*128 + (idx & 127)];
}

// RBF straight into flat-task fragment layout; one warp per (m, t)
__global__ void k_init_ea(const float* __restrict__ coords){
    int gw = (blockIdx.x*256 + threadIdx.x) >> 5;   // m*18 + t
    int lane = threadIdx.x & 31, q = lane>>2, cp = lane&3;
    int m = gw/18, t = gw - m*18;
    const float* cm = coords + (size_t)m*72;
    float dist[4];
    #pragma unroll
    for (int i=0;i<4;++i){
        int row = t*32 + (i&1)*8 + (i>>1)*16 + q;
        int d = row/24, s = row - d*24;
        float ax=cm[s*3]-cm[d*3], ay=cm[s*3+1]-cm[d*3+1], az=cm[s*3+2]-cm[d*3+2];
        dist[i] = sqrtf(ax*ax+ay*ay+az*az);
    }
    const float delta = 10.f/127.f, coeff = -0.5f/(delta*delta);
    u32* base = g_EAf + (size_t)gw*4096;
    #pragma unroll
    for (int ks=0; ks<8; ++ks){
        float c0 = (float)(16*ks + 2*cp);
        float v[4][4];
        #pragma unroll
        for (int i=0;i<4;++i)
            #pragma unroll
            for (int j=0;j<4;++j){
                float od = dist[i] - delta*(c0 + (float)((j>>1)*8 + (j&1)));
                v[i][j] = (fabsf(od) < 1.2f) ? __expf(coeff*od*od) : 0.f;
            }
        u32 h[4],l[4],h2[4],l2[4];
        sp2(v[0][0],v[0][1],h[0],l[0]);  sp2(v[1][0],v[1][1],h[1],l[1]);
        sp2(v[0][2],v[0][3],h[2],l[2]);  sp2(v[1][2],v[1][3],h[3],l[3]);
        sp2(v[2][0],v[2][1],h2[0],l2[0]); sp2(v[3][0],v[3][1],h2[1],l2[1]);
        sp2(v[2][2],v[2][3],h2[2],l2[2]); sp2(v[3][2],v[3][3],h2[3],l2[3]);
        u32* c = base + ks*512;
        *(uint4*)(c + lane*4)       = make_uint4(h[0],h[1],h[2],h[3]);
        *(uint4*)(c + 128 + lane*4) = make_uint4(h2[0],h2[1],h2[2],h2[3]);
        *(uint4*)(c + 256 + lane*4) = make_uint4(l[0],l[1],l[2],l[3]);
        *(uint4*)(c + 384 + lane*4) = make_uint4(l2[0],l2[1],l2[2],l2[3]);
    }
}

__global__ void __launch_bounds__(256,1) k_x_mma(){
    extern __shared__ __align__(16) char sm[];
    char *Wh = sm, *Wl = sm+IMG, *Ah = sm+2*IMG, *Al = sm+3*IMG;
    const int tid = threadIdx.x, wid = tid>>5, lane = tid&31, R = wid*16;
    for (int i = tid; i < 2048; i += 256){
        int k = i>>4, ch = i&15; u32 d = k*PIT + ch*16;
        cpa16(smaddr(Wh)+d, g_Wimg[0][0]+i*16);
        cpa16(smaddr(Wl)+d, g_Wimg[0][1]+i*16);
    }
    CP_COMMIT; CP_WAIT0; __syncthreads();
    size_t rowbase = (size_t)blockIdx.x * 128;
    stage_band(g_h + rowbase*128, Ah, Al, R, lane);
    __syncwarp();
    float acc[16][4]; zacc16(acc);
    wgemm3(acc, smaddr(Ah)+R*PIT, smaddr(Al)+R*PIT, smaddr(Wh), smaddr(Wl), lane);
    int r0 = (int)rowbase + R + (lane>>2), cb = (lane&3)*2;
    #pragma unroll
    for (int nb = 0; nb < 16; ++nb){
        int c = nb*8 + cb;
        *(float2*)(g_x + (size_t)r0*128 + c)     = make_float2(acc[nb][0], acc[nb][1]);
        *(float2*)(g_x + (size_t)(r0+8)*128 + c) = make_float2(acc[nb][2], acc[nb][3]);
    }
}

// edge kernel: 192 thr = 6 warps x 3 tasks of 32 flat rows (no padding)
__global__ void __launch_bounds__(192,1) k_edge(const float* __restrict__ eb1, const float* __restrict__ eb2){
    extern __shared__ __align__(16) char sm[];
    char *W1h=sm, *W1l=sm+IMG, *W2h=sm+2*IMG, *W2l=sm+3*IMG;
    float* xs   = (float*)(sm+4*IMG);           // 24 x 132
    float* sagg = xs + 24*132;                  // 24 x 132
    float* b1s  = sagg + 24*132; float* b2s = b1s + 128;
    const int tid=threadIdx.x, m=blockIdx.x;
    const int wid=tid>>5, lane=tid&31, q=lane>>2, cp=lane&3;
    for (int i=tid;i<2048;i+=192){
        int k=i>>4, ch=i&15; u32 dof=k*PIT+ch*16;
        cpa16(smaddr(W1h)+dof, g_Wimg[1][0]+i*16);
        cpa16(smaddr(W1l)+dof, g_Wimg[1][1]+i*16);
        cpa16(smaddr(W2h)+dof, g_Wimg[2][0]+i*16);
        cpa16(smaddr(W2l)+dof, g_Wimg[2][1]+i*16);
    }
    CP_COMMIT;
    for (int i=tid;i<Aat*128;i+=192) xs[(i>>7)*132+(i&127)] = g_x[(size_t)m*3072+i];
    for (int i=tid;i<24*132;i+=192) sagg[i]=0.f;
    if (tid<128){ b1s[tid]=eb1[tid]; b2s[tid]=eb2[tid]; }
    CP_WAIT0; __syncthreads();

    const u32 sW1h=smaddr(W1h), sW1l=smaddr(W1l), sW2h=smaddr(W2h), sW2l=smaddr(W2l);
    const u32 loff = (lane&15)*PIT + (lane>>4)*16;

    for (int it=0; it<3; ++it){
        const int t = wid + it*6;
        u32* base = g_EAf + ((size_t)(m*18 + t))*4096;
        // per-lane row meta: i=0: q, 1: q+8 (mb0); 2: 16+q, 3: 24+q (mb1)
        int rs[4], rd[4]; bool dg[4];
        #pragma unroll
        for (int i=0;i<4;++i){
            int row = t*32 + (i&1)*8 + (i>>1)*16 + q;
            rd[i] = row/24; rs[i] = row - rd[i]*24; dg[i] = (rs[i]==rd[i]);
        }

        float acc1[2][16][4];
        zacc16(acc1[0]); zacc16(acc1[1]);
        uint4 H0=*(const uint4*)(base+lane*4),     H1=*(const uint4*)(base+128+lane*4);
        uint4 L0=*(const uint4*)(base+256+lane*4), L1=*(const uint4*)(base+384+lane*4);
        #pragma unroll
        for (int ks=0;ks<8;++ks){
            uint4 nH0,nH1,nL0,nL1;
            if (ks<7){
                const u32* nb = base+(ks+1)*512;
                nH0=*(const uint4*)(nb+lane*4);     nH1=*(const uint4*)(nb+128+lane*4);
                nL0=*(const uint4*)(nb+256+lane*4); nL1=*(const uint4*)(nb+384+lane*4);
            }
            u32 ah0[4]={H0.x,H0.y,H0.z,H0.w}, ah1[4]={H1.x,H1.y,H1.z,H1.w};
            u32 al0[4]={L0.x,L0.y,L0.z,L0.w}, al1[4]={L1.x,L1.y,L1.z,L1.w};
            #pragma unroll
            for (int j=0;j<8;++j){
                u32 bh[4],bl[4]; u32 ba=loff+ks*(16*PIT)+j*32;
                ldsm4t(bh,sW1h+ba); ldsm4t(bl,sW1l+ba);
                mma_bf(acc1[0][2*j],   ah0,bh[0],bh[1]); mma_bf(acc1[0][2*j],   ah0,bl[0],bl[1]); mma_bf(acc1[0][2*j],   al0,bh[0],bh[1]);
                mma_bf(acc1[0][2*j+1], ah0,bh[2],bh[3]); mma_bf(acc1[0][2*j+1], ah0,bl[2],bl[3]); mma_bf(acc1[0][2*j+1], al0,bh[2],bh[3]);
                mma_bf(acc1[1][2*j],   ah1,bh[0],bh[1]); mma_bf(acc1[1][2*j],   ah1,bl[0],bl[1]); mma_bf(acc1[1][2*j],   al1,bh[0],bh[1]);
                mma_bf(acc1[1][2*j+1], ah1,bh[2],bh[3]); mma_bf(acc1[1][2*j+1], ah1,bl[2],bl[3]); mma_bf(acc1[1][2*j+1], al1,bh[2],bh[3]);
            }
            if (ks<7){ H0=nH0; H1=nH1; L0=nL0; L1=nL1; }
        }
        u32 a2h[2][8][4], a2l[2][8][4];
        #pragma unroll
        for (int mb=0;mb<2;++mb)
            #pragma unroll
            for (int j=0;j<8;++j){
                int c0=16*j+2*cp;
                float bA0=b1s[c0], bA1=b1s[c0+1], bB0=b1s[c0+8], bB1=b1s[c0+9];
                sp2(ssp(acc1[mb][2*j][0]+bA0),   ssp(acc1[mb][2*j][1]+bA1),   a2h[mb][j][0], a2l[mb][j][0]);
                sp2(ssp(acc1[mb][2*j][2]+bA0),   ssp(acc1[mb][2*j][3]+bA1),   a2h[mb][j][1], a2l[mb][j][1]);
                sp2(ssp(acc1[mb][2*j+1][0]+bB0), ssp(acc1[mb][2*j+1][1]+bB1), a2h[mb][j][2], a2l[mb][j][2]);
                sp2(ssp(acc1[mb][2*j+1][2]+bB0), ssp(acc1[mb][2*j+1][3]+bB1), a2h[mb][j][3], a2l[mb][j][3]);
            }
        #pragma unroll
        for (int hf=0; hf<2; ++hf){
            float acc2[2][8][4];
            #pragma unroll
            for (int mb=0;mb<2;++mb)
                #pragma unroll
                for (int i=0;i<8;++i){ acc2[mb][i][0]=0;acc2[mb][i][1]=0;acc2[mb][i][2]=0;acc2[mb][i][3]=0; }
            #pragma unroll
            for (int ks=0;ks<8;++ks)
                #pragma unroll
                for (int j=0;j<4;++j){
                    u32 bh[4],bl[4]; u32 ba=loff+ks*(16*PIT)+(hf*4+j)*32;
                    ldsm4t(bh,sW2h+ba); ldsm4t(bl,sW2l+ba);
                    #pragma unroll
                    for (int mb=0;mb<2;++mb){
                        mma_bf(acc2[mb][2*j],   a2h[mb][ks],bh[0],bh[1]);
                        mma_bf(acc2[mb][2*j],   a2h[mb][ks],bl[0],bl[1]);
                        mma_bf(acc2[mb][2*j],   a2l[mb][ks],bh[0],bh[1]);
                        mma_bf(acc2[mb][2*j+1], a2h[mb][ks],bh[2],bh[3]);
                        mma_bf(acc2[mb][2*j+1], a2h[mb][ks],bl[2],bl[3]);
                        mma_bf(acc2[mb][2*j+1], a2l[mb][ks],bh[2],bh[3]);
                    }
                }
            #pragma unroll
            for (int mb=0;mb<2;++mb){
                int i0 = mb*2, i1 = mb*2+1;
                #pragma unroll
                for (int j=0;j<4;++j){
                    int cA=hf*64+16*j+2*cp, cB=cA+8;
                    float bA0=b2s[cA],bA1=b2s[cA+1],bB0=b2s[cB],bB1=b2s[cB+1];
                    float v00=(acc2[mb][2*j][0]+bA0)*xs[rs[i0]*132+cA];
                    float v01=(acc2[mb][2*j][1]+bA1)*xs[rs[i0]*132+cA+1];
                    float v10=(acc2[mb][2*j][2]+bA0)*xs[rs[i1]*132+cA];
                    float v11=(acc2[mb][2*j][3]+bA1)*xs[rs[i1]*132+cA+1];
                    float w00=(acc2[mb][2*j+1][0]+bB0)*xs[rs[i0]*132+cB];
                    float w01=(acc2[mb][2*j+1][1]+bB1)*xs[rs[i0]*132+cB+1];
                    float w10=(acc2[mb][2*j+1][2]+bB0)*xs[rs[i1]*132+cB];
                    float w11=(acc2[mb][2*j+1][3]+bB1)*xs[rs[i1]*132+cB+1];
                    if(!dg[i0]){
                        atomicAdd(&sagg[rd[i0]*132+cA],   v00); atomicAdd(&sagg[rd[i0]*132+cA+1], v01);
                        atomicAdd(&sagg[rd[i0]*132+cB],   w00); atomicAdd(&sagg[rd[i0]*132+cB+1], w01);
                    }
                    if(!dg[i1]){
                        atomicAdd(&sagg[rd[i1]*132+cA],   v10); atomicAdd(&sagg[rd[i1]*132+cA+1], v11);
                        atomicAdd(&sagg[rd[i1]*132+cB],   w10); atomicAdd(&sagg[rd[i1]*132+cB+1], w11);
                    }
                    u32 h4[4],l4[4];
                    sp2(v00,v01,h4[0],l4[0]); sp2(v10,v11,h4[1],l4[1]);
                    sp2(w00,w01,h4[2],l4[2]); sp2(w10,w11,h4[3],l4[3]);
                    u32* c = base + (hf*4+j)*512 + mb*128;
                    *(uint4*)(c+lane*4)     = make_uint4(h4[0],h4[1],h4[2],h4[3]);
                    *(uint4*)(c+256+lane*4) = make_uint4(l4[0],l4[1],l4[2],l4[3]);
                }
            }
        }
    }
    __syncthreads();
    for (int i=tid;i<Aat*128;i+=192)
        g_agg[(size_t)m*3072 + i] = sagg[(i>>7)*132 + (i&127)];
}

__global__ void __launch_bounds__(256,1) k_node_mma(const float* __restrict__ nb1, const float* __restrict__ nb2){
    extern __shared__ __align__(16) char sm[];
    char *W1h = sm, *W1l = sm+IMG, *W2h = sm+2*IMG, *W2l = sm+3*IMG;
    char *Ah = sm+4*IMG, *Al = sm+5*IMG;
    float* b1s = (float*)(sm + 6*IMG); float* b2s = b1s + 128;
    const int tid = threadIdx.x, wid = tid>>5, lane = tid&31, R = wid*16;
    for (int i = tid; i < 2048; i += 256){
        int k = i>>4, ch = i&15; u32 d = k*PIT + ch*16;
        cpa16(smaddr(W1h)+d, g_Wimg[3][0]+i*16);
        cpa16(smaddr(W1l)+d, g_Wimg[3][1]+i*16);
        cpa16(smaddr(W2h)+d, g_Wimg[4][0]+i*16);
        cpa16(smaddr(W2l)+d, g_Wimg[4][1]+i*16);
    }
    CP_COMMIT;
    if (tid < 128){ b1s[tid] = nb1[tid]; b2s[tid] = nb2[tid]; }
    CP_WAIT0; __syncthreads();
    size_t rowbase = (size_t)blockIdx.x * 128;
    stage_band(g_agg + rowbase*128, Ah, Al, R, lane);
    __syncwarp();
    float acc[16][4]; zacc16(acc);
    wgemm3(acc, smaddr(Ah)+R*PIT, smaddr(Al)+R*PIT, smaddr(W1h), smaddr(W1l), lane);
    write_mid(acc, b1s, Ah, Al, R, lane);
    __syncwarp();
    zacc16(acc);
    wgemm3(acc, smaddr(Ah)+R*PIT, smaddr(Al)+R*PIT, smaddr(W2h), smaddr(W2l), lane);
    int r0 = (int)rowbase + R + (lane>>2), cb = (lane&3)*2;
    #pragma unroll
    for (int nb = 0; nb < 16; ++nb){
        int c = nb*8 + cb;
        float bx = b2s[c], by = b2s[c+1];
        float2 h0 = *(float2*)(g_h + (size_t)r0*128 + c);
        float2 h1 = *(float2*)(g_h + (size_t)(r0+8)*128 + c);
        h0.x += acc[nb][0] + bx;  h0.y += acc[nb][1] + by;
        h1.x += acc[nb][2] + bx;  h1.y += acc[nb][3] + by;
        *(float2*)(g_h + (size_t)r0*128 + c)     = h0;
        *(float2*)(g_h + (size_t)(r0+8)*128 + c) = h1;
    }
}

__global__ void __launch_bounds__(256) k_graph(const float* __restrict__ gw1, const float* __restrict__ gb1,
                                               const float* __restrict__ gw2, const float* __restrict__ gb2,
                                               float* __restrict__ out)
{
    __shared__ float hs[Aat*128];
    __shared__ float w1s[128*64];
    __shared__ float red[256];
    const int tid = threadIdx.x, m = blockIdx.x;
    {
        const float4* hg = (const float4*)(g_h + (size_t)m*Aat*128);
        for (int i = tid; i < 768; i += 256) ((float4*)hs)[i] = hg[i];
        const float4* wg = (const float4*)gw1;
        for (int i = tid; i < 2048; i += 256) ((float4*)w1s)[i] = wg[i];
    }
    __syncthreads();
    float local = 0.f;
    for (int pos = tid; pos < Aat*64; pos += 256){
        int s = pos >> 6, c = pos & 63;
        float acc = gb1[c];
        #pragma unroll 16
        for (int k = 0; k < 128; ++k) acc += hs[s*128+k] * w1s[k*64+c];
        local += ssp(acc) * gw2[c];
    }
    red[tid] = local;
    __syncthreads();
    #pragma unroll
    for (int off = 128; off > 0; off >>= 1){
        if (tid < off) red[tid] += red[tid+off];
        __syncthreads();
    }
    if (tid == 0) out[m] = red[0] + (float)Aat * gb2[0];
}

extern "C" void kernel_launch(void* const* d_in, const int* in_sizes, int n_in,
                              void* d_out, int out_size)
{
    const int*   charges = (const int*)  d_in[0];
    const float* coords  = (const float*)d_in[1];
    const float* emb = (const float*)d_in[4];
    const float* nlw = (const float*)d_in[5];
    const float* ew1 = (const float*)d_in[6];
    const float* eb1 = (const float*)d_in[7];
    const float* ew2 = (const float*)d_in[8];
    const float* eb2 = (const float*)d_in[9];
    const float* nw1 = (const float*)d_in[10];
    const float* nb1 = (const float*)d_in[11];
    const float* nw2 = (const float*)d_in[12];
    const float* nb2 = (const float*)d_in[13];
    const float* gw1 = (const float*)d_in[14];
    const float* gb1 = (const float*)d_in[15];
    const float* gw2 = (const float*)d_in[16];
    const float* gb2 = (const float*)d_in[17];
    float* out = (float*)d_out;

    const int SME = 4*IMG + (24*132*2 + 256)*4;   // 165632
    const int SMN = 6*IMG + 1024;                 // 209920
    const int SMX = 4*IMG;                        // 139264
    cudaFuncSetAttribute(k_edge,     cudaFuncAttributeMaxDynamicSharedMemorySize, SME);
    cudaFuncSetAttribute(k_node_mma, cudaFuncAttributeMaxDynamicSharedMemorySize, SMN);
    cudaFuncSetAttribute(k_x_mma,    cudaFuncAttributeMaxDynamicSharedMemorySize, SMX);

    k_init   <<<5 + (Nnode*128)/256, 256>>>(charges, emb, nlw, ew1, ew2, nw1, nw2);
    k_init_ea<<<(Mmol*18)/8, 256>>>(coords);

    for (int l = 0; l < 4; ++l) {
        k_x_mma   <<<384,  256, SMX>>>();
        k_edge    <<<Mmol, 192, SME>>>(eb1, eb2);
        k_node_mma<<<384,  256, SMN>>>(nb1, nb2);
    }
    k_graph<<<Mmol, 256>>>(gw1, gb1, gw2, gb2, out);
}

// round 8
// speedup vs baseline: 1.1996x; 1.1996x over previous
#include <cuda_runtime.h>
#include <cuda_bf16.h>

typedef unsigned int u32; typedef unsigned long long u64;
#define Mmol 2048
#define Aat 24
#define Nnode (Mmol*Aat)
#define PIT 272
#define IMG 34816

// EA per (m, task t of 18): 8 ks-chunks of 512 u32: [hi mb0|hi mb1|lo mb0|lo mb1] x 128
__device__ u32   g_EAf[(size_t)Mmol*18*4096];   // 604 MB
__device__ float g_h  [(size_t)Nnode*128];
__device__ float g_x  [(size_t)Nnode*128];
__device__ float g_agg[(size_t)Nnode*128];
__device__ __align__(16) unsigned char g_Wimg[5][2][32768];

__device__ __forceinline__ u32 smaddr(const void* p){
    u32 a; asm("{ .reg .u64 t; cvta.to.shared.u64 t, %1; cvt.u32.u64 %0, t; }" : "=r"(a) : "l"(p)); return a;
}
__device__ __forceinline__ float ssp(float x){
    return fmaxf(x, 0.f) + __logf(1.f + __expf(-fabsf(x))) - 0.6931471805599453f;
}
__device__ __forceinline__ void cpa16(u32 dst, const void* src){
    asm volatile("cp.async.cg.shared.global [%0], [%1], 16;" :: "r"(dst), "l"(src) : "memory");
}
#define CP_COMMIT asm volatile("cp.async.commit_group;" ::: "memory")
#define CP_WAIT0  asm volatile("cp.async.wait_group 0;"  ::: "memory")
__device__ __forceinline__ void ldsm4(u32* r, u32 a){
    asm volatile("ldmatrix.sync.aligned.m8n8.x4.shared.b16 {%0,%1,%2,%3}, [%4];"
        : "=r"(r[0]),"=r"(r[1]),"=r"(r[2]),"=r"(r[3]) : "r"(a));
}
__device__ __forceinline__ void ldsm4t(u32* r, u32 a){
    asm volatile("ldmatrix.sync.aligned.m8n8.x4.trans.shared.b16 {%0,%1,%2,%3}, [%4];"
        : "=r"(r[0]),"=r"(r[1]),"=r"(r[2]),"=r"(r[3]) : "r"(a));
}
__device__ __forceinline__ void mma_bf(float* d, const u32* a, u32 b0, u32 b1){
    asm volatile("mma.sync.aligned.m16n8k16.row.col.f32.bf16.bf16.f32 "
        "{%0,%1,%2,%3}, {%4,%5,%6,%7}, {%8,%9}, {%0,%1,%2,%3};"
        : "+f"(d[0]),"+f"(d[1]),"+f"(d[2]),"+f"(d[3])
        : "r"(a[0]),"r"(a[1]),"r"(a[2]),"r"(a[3]),"r"(b0),"r"(b1));
}
__device__ __forceinline__ void sp2(float x, float y, u32& h, u32& l){
    __nv_bfloat162 hb = __floats2bfloat162_rn(x, y);
    __nv_bfloat162 lb = __floats2bfloat162_rn(x - __bfloat162float(hb.x), y - __bfloat162float(hb.y));
    h = *(u32*)&hb; l = *(u32*)&lb;
}
__device__ __forceinline__ void stage_band(const float* __restrict__ src, char* Ah, char* Al, int R, int lane){
    #pragma unroll 4
    for (int i = 0; i < 16; ++i){
        int row = R + i;
        float4 v = ((const float4*)src)[row*32 + lane];
        u32 h0,l0,h1,l1; sp2(v.x,v.y,h0,l0); sp2(v.z,v.w,h1,l1);
        int o = row*PIT + lane*8;
        *(uint2*)(Ah+o) = make_uint2(h0,h1);
        *(uint2*)(Al+o) = make_uint2(l0,l1);
    }
}
__device__ __forceinline__ void wgemm3(float acc[16][4], u32 baseAh, u32 baseAl,
                                       u32 baseBh, u32 baseBl, int lane){
    u32 off = (lane & 15)*PIT + (lane >> 4)*16;
    #pragma unroll
    for (int ks = 0; ks < 8; ++ks){
        u32 ah[4], al[4];
        ldsm4(ah, baseAh + off + ks*32);
        ldsm4(al, baseAl + off + ks*32);
        #pragma unroll
        for (int nb = 0; nb < 8; ++nb){
            u32 bh[4], bl[4];
            u32 ba = off + ks*(16*PIT) + nb*32;
            ldsm4t(bh, baseBh + ba); ldsm4t(bl, baseBl + ba);
            mma_bf(acc[nb*2],   ah, bh[0], bh[1]);
            mma_bf(acc[nb*2],   ah, bl[0], bl[1]);
            mma_bf(acc[nb*2],   al, bh[0], bh[1]);
            mma_bf(acc[nb*2+1], ah, bh[2], bh[3]);
            mma_bf(acc[nb*2+1], ah, bl[2], bl[3]);
            mma_bf(acc[nb*2+1], al, bh[2], bh[3]);
        }
    }
}
__device__ __forceinline__ void zacc16(float acc[16][4]){
    #pragma unroll
    for (int i=0;i<16;++i){ acc[i][0]=0.f;acc[i][1]=0.f;acc[i][2]=0.f;acc[i][3]=0.f; }
}
__device__ __forceinline__ void write_mid(const float acc[16][4], const float* b1s,
                                          char* Ah, char* Al, int R, int lane){
    int r0 = R + (lane>>2), cb = (lane&3)*2;
    #pragma unroll
    for (int nb = 0; nb < 16; ++nb){
        int c = nb*8 + cb;
        float bx = b1s[c], by = b1s[c+1];
        u32 h0,l0,h1,l1;
        sp2(ssp(acc[nb][0]+bx), ssp(acc[nb][1]+by), h0, l0);
        sp2(ssp(acc[nb][2]+bx), ssp(acc[nb][3]+by), h1, l1);
        *(u32*)(Ah + r0*PIT + c*2) = h0;     *(u32*)(Al + r0*PIT + c*2) = l0;
        *(u32*)(Ah + (r0+8)*PIT + c*2) = h1; *(u32*)(Al + (r0+8)*PIT + c*2) = l1;
    }
}

__global__ void k_init(const int* __restrict__ charges, const float* __restrict__ emb,
                       const float* nlw, const float* ew1, const float* ew2,
                       const float* nw1, const float* nw2){
    if (blockIdx.x < 5){
        if (threadIdx.x >= 128) return;
        const float* srcs[5] = {nlw, ew1, ew2, nw1, nw2};
        const float* src = srcs[blockIdx.x];
        int n = threadIdx.x;
        for (int k = 0; k < 128; ++k){
            float v = src[k*128 + n];
            __nv_bfloat16 h = __float2bfloat16_rn(v);
            __nv_bfloat16 l = __float2bfloat16_rn(v - __bfloat162float(h));
            *(__nv_bfloat16*)(g_Wimg[blockIdx.x][0] + k*256 + n*2) = h;
            *(__nv_bfloat16*)(g_Wimg[blockIdx.x][1] + k*256 + n*2) = l;
        }
        return;
    }
    int idx = (blockIdx.x-5)*256 + threadIdx.x;
    g_h[idx] = emb[charges[idx>>7]*128 + (idx & 127)];
}

// RBF straight into flat-task fragment layout; one warp per (m, t)
__global__ void k_init_ea(const float* __restrict__ coords){
    int gw = (blockIdx.x*256 + threadIdx.x) >> 5;   // m*18 + t
    int lane = threadIdx.x & 31, q = lane>>2, cp = lane&3;
    int m = gw/18, t = gw - m*18;
    const float* cm = coords + (size_t)m*72;
    float dist[4];
    #pragma unroll
    for (int i=0;i<4;++i){
        int row = t*32 + (i&1)*8 + (i>>1)*16 + q;
        int d = row/24, s = row - d*24;
        float ax=cm[s*3]-cm[d*3], ay=cm[s*3+1]-cm[d*3+1], az=cm[s*3+2]-cm[d*3+2];
        dist[i] = sqrtf(ax*ax+ay*ay+az*az);
    }
    const float delta = 10.f/127.f, coeff = -0.5f/(delta*delta);
    u32* base = g_EAf + (size_t)gw*4096;
    #pragma unroll
    for (int ks=0; ks<8; ++ks){
        float c0 = (float)(16*ks + 2*cp);
        float v[4][4];
        #pragma unroll
        for (int i=0;i<4;++i)
            #pragma unroll
            for (int j=0;j<4;++j){
                float od = dist[i] - delta*(c0 + (float)((j>>1)*8 + (j&1)));
                v[i][j] = (fabsf(od) < 1.2f) ? __expf(coeff*od*od) : 0.f;
            }
        u32 h[4],l[4],h2[4],l2[4];
        sp2(v[0][0],v[0][1],h[0],l[0]);  sp2(v[1][0],v[1][1],h[1],l[1]);
        sp2(v[0][2],v[0][3],h[2],l[2]);  sp2(v[1][2],v[1][3],h[3],l[3]);
        sp2(v[2][0],v[2][1],h2[0],l2[0]); sp2(v[3][0],v[3][1],h2[1],l2[1]);
        sp2(v[2][2],v[2][3],h2[2],l2[2]); sp2(v[3][2],v[3][3],h2[3],l2[3]);
        u32* c = base + ks*512;
        *(uint4*)(c + lane*4)       = make_uint4(h[0],h[1],h[2],h[3]);
        *(uint4*)(c + 128 + lane*4) = make_uint4(h2[0],h2[1],h2[2],h2[3]);
        *(uint4*)(c + 256 + lane*4) = make_uint4(l[0],l[1],l[2],l[3]);
        *(uint4*)(c + 384 + lane*4) = make_uint4(l2[0],l2[1],l2[2],l2[3]);
    }
}

__global__ void __launch_bounds__(256,1) k_x_mma(){
    extern __shared__ __align__(16) char sm[];
    char *Wh = sm, *Wl = sm+IMG, *Ah = sm+2*IMG, *Al = sm+3*IMG;
    const int tid = threadIdx.x, wid = tid>>5, lane = tid&31, R = wid*16;
    for (int i = tid; i < 2048; i += 256){
        int k = i>>4, ch = i&15; u32 d = k*PIT + ch*16;
        cpa16(smaddr(Wh)+d, g_Wimg[0][0]+i*16);
        cpa16(smaddr(Wl)+d, g_Wimg[0][1]+i*16);
    }
    CP_COMMIT; CP_WAIT0; __syncthreads();
    size_t rowbase = (size_t)blockIdx.x * 128;
    stage_band(g_h + rowbase*128, Ah, Al, R, lane);
    __syncwarp();
    float acc[16][4]; zacc16(acc);
    wgemm3(acc, smaddr(Ah)+R*PIT, smaddr(Al)+R*PIT, smaddr(Wh), smaddr(Wl), lane);
    int r0 = (int)rowbase + R + (lane>>2), cb = (lane&3)*2;
    #pragma unroll
    for (int nb = 0; nb < 16; ++nb){
        int c = nb*8 + cb;
        *(float2*)(g_x + (size_t)r0*128 + c)     = make_float2(acc[nb][0], acc[nb][1]);
        *(float2*)(g_x + (size_t)(r0+8)*128 + c) = make_float2(acc[nb][2], acc[nb][3]);
    }
}

// edge kernel: 288 thr = 9 warps x 2 tasks of 32 flat rows (no padding)
__global__ void __launch_bounds__(288,1) k_edge(const float* __restrict__ eb1, const float* __restrict__ eb2){
    extern __shared__ __align__(16) char sm[];
    char *W1h=sm, *W1l=sm+IMG, *W2h=sm+2*IMG, *W2l=sm+3*IMG;
    float* xs   = (float*)(sm+4*IMG);           // 24 x 132
    float* sagg = xs + 24*132;                  // 24 x 132
    float* b1s  = sagg + 24*132; float* b2s = b1s + 128;
    const int tid=threadIdx.x, m=blockIdx.x;
    const int wid=tid>>5, lane=tid&31, q=lane>>2, cp=lane&3;
    for (int i=tid;i<2048;i+=288){
        int k=i>>4, ch=i&15; u32 dof=k*PIT+ch*16;
        cpa16(smaddr(W1h)+dof, g_Wimg[1][0]+i*16);
        cpa16(smaddr(W1l)+dof, g_Wimg[1][1]+i*16);
        cpa16(smaddr(W2h)+dof, g_Wimg[2][0]+i*16);
        cpa16(smaddr(W2l)+dof, g_Wimg[2][1]+i*16);
    }
    CP_COMMIT;
    for (int i=tid;i<Aat*128;i+=288) xs[(i>>7)*132+(i&127)] = g_x[(size_t)m*3072+i];
    for (int i=tid;i<24*132;i+=288) sagg[i]=0.f;
    if (tid<128){ b1s[tid]=eb1[tid]; b2s[tid]=eb2[tid]; }
    CP_WAIT0; __syncthreads();

    const u32 sW1h=smaddr(W1h), sW1l=smaddr(W1l), sW2h=smaddr(W2h), sW2l=smaddr(W2l);
    const u32 loff = (lane&15)*PIT + (lane>>4)*16;

    for (int it=0; it<2; ++it){
        const int T = wid + it*9;               // task 0..17, 32 flat rows
        u32* base = g_EAf + ((size_t)(m*18 + T))*4096;

        // ---- GEMM1 in two n-halves, immediate a2 conversion (reg-lean) ----
        u32 a2h[2][8][4], a2l[2][8][4];
        #pragma unroll
        for (int half=0; half<2; ++half){
            float acc1[2][8][4];
            #pragma unroll
            for (int i=0;i<8;++i){
                acc1[0][i][0]=0;acc1[0][i][1]=0;acc1[0][i][2]=0;acc1[0][i][3]=0;
                acc1[1][i][0]=0;acc1[1][i][1]=0;acc1[1][i][2]=0;acc1[1][i][3]=0;
            }
            uint4 H0=*(const uint4*)(base+lane*4),     H1=*(const uint4*)(base+128+lane*4);
            uint4 L0=*(const uint4*)(base+256+lane*4), L1=*(const uint4*)(base+384+lane*4);
            #pragma unroll
            for (int ks=0;ks<8;++ks){
                uint4 nH0,nH1,nL0,nL1;
                if (ks<7){
                    const u32* nb = base+(ks+1)*512;
                    nH0=*(const uint4*)(nb+lane*4);     nH1=*(const uint4*)(nb+128+lane*4);
                    nL0=*(const uint4*)(nb+256+lane*4); nL1=*(const uint4*)(nb+384+lane*4);
                }
                u32 ah0[4]={H0.x,H0.y,H0.z,H0.w}, ah1[4]={H1.x,H1.y,H1.z,H1.w};
                u32 al0[4]={L0.x,L0.y,L0.z,L0.w}, al1[4]={L1.x,L1.y,L1.z,L1.w};
                #pragma unroll
                for (int j=0;j<4;++j){
                    int jj = half*4 + j;
                    u32 bh[4],bl[4]; u32 ba=loff+ks*(16*PIT)+jj*32;
                    ldsm4t(bh,sW1h+ba); ldsm4t(bl,sW1l+ba);
                    mma_bf(acc1[0][2*j],   ah0,bh[0],bh[1]); mma_bf(acc1[0][2*j],   ah0,bl[0],bl[1]); mma_bf(acc1[0][2*j],   al0,bh[0],bh[1]);
                    mma_bf(acc1[0][2*j+1], ah0,bh[2],bh[3]); mma_bf(acc1[0][2*j+1], ah0,bl[2],bl[3]); mma_bf(acc1[0][2*j+1], al0,bh[2],bh[3]);
                    mma_bf(acc1[1][2*j],   ah1,bh[0],bh[1]); mma_bf(acc1[1][2*j],   ah1,bl[0],bl[1]); mma_bf(acc1[1][2*j],   al1,bh[0],bh[1]);
                    mma_bf(acc1[1][2*j+1], ah1,bh[2],bh[3]); mma_bf(acc1[1][2*j+1], ah1,bl[2],bl[3]); mma_bf(acc1[1][2*j+1], al1,bh[2],bh[3]);
                }
                if (ks<7){ H0=nH0; H1=nH1; L0=nL0; L1=nL1; }
            }
            #pragma unroll
            for (int mb=0;mb<2;++mb)
                #pragma unroll
                for (int j=0;j<4;++j){
                    int jj = half*4 + j;
                    int c0 = 16*jj + 2*cp;
                    float bA0=b1s[c0], bA1=b1s[c0+1], bB0=b1s[c0+8], bB1=b1s[c0+9];
                    sp2(ssp(acc1[mb][2*j][0]+bA0),   ssp(acc1[mb][2*j][1]+bA1),   a2h[mb][jj][0], a2l[mb][jj][0]);
                    sp2(ssp(acc1[mb][2*j][2]+bA0),   ssp(acc1[mb][2*j][3]+bA1),   a2h[mb][jj][1], a2l[mb][jj][1]);
                    sp2(ssp(acc1[mb][2*j+1][0]+bB0), ssp(acc1[mb][2*j+1][1]+bB1), a2h[mb][jj][2], a2l[mb][jj][2]);
                    sp2(ssp(acc1[mb][2*j+1][2]+bB0), ssp(acc1[mb][2*j+1][3]+bB1), a2h[mb][jj][3], a2l[mb][jj][3]);
                }
        }

        // ---- GEMM2 in two n-halves + fused epilogue ----
        #pragma unroll
        for (int hf=0; hf<2; ++hf){
            float acc2[2][8][4];
            #pragma unroll
            for (int i=0;i<8;++i){
                acc2[0][i][0]=0;acc2[0][i][1]=0;acc2[0][i][2]=0;acc2[0][i][3]=0;
                acc2[1][i][0]=0;acc2[1][i][1]=0;acc2[1][i][2]=0;acc2[1][i][3]=0;
            }
            #pragma unroll
            for (int ks=0;ks<8;++ks)
                #pragma unroll
                for (int j=0;j<4;++j){
                    u32 bh[4],bl[4]; u32 ba=loff+ks*(16*PIT)+(hf*4+j)*32;
                    ldsm4t(bh,sW2h+ba); ldsm4t(bl,sW2l+ba);
                    #pragma unroll
                    for (int mb=0;mb<2;++mb){
                        mma_bf(acc2[mb][2*j],   a2h[mb][ks],bh[0],bh[1]);
                        mma_bf(acc2[mb][2*j],   a2h[mb][ks],bl[0],bl[1]);
                        mma_bf(acc2[mb][2*j],   a2l[mb][ks],bh[0],bh[1]);
                        mma_bf(acc2[mb][2*j+1], a2h[mb][ks],bh[2],bh[3]);
                        mma_bf(acc2[mb][2*j+1], a2h[mb][ks],bl[2],bl[3]);
                        mma_bf(acc2[mb][2*j+1], a2l[mb][ks],bh[2],bh[3]);
                    }
                }
            #pragma unroll
            for (int mb=0;mb<2;++mb){
                int row0 = T*32 + mb*16 + q;
                int d0 = row0/24,    s0 = row0 - d0*24;
                int row1 = row0 + 8;
                int d1 = row1/24,    s1 = row1 - d1*24;
                #pragma unroll
                for (int j=0;j<4;++j){
                    int cA=hf*64+16*j+2*cp, cB=cA+8;
                    float bA0=b2s[cA],bA1=b2s[cA+1],bB0=b2s[cB],bB1=b2s[cB+1];
                    float v00=(acc2[mb][2*j][0]+bA0)*xs[s0*132+cA];
                    float v01=(acc2[mb][2*j][1]+bA1)*xs[s0*132+cA+1];
                    float v10=(acc2[mb][2*j][2]+bA0)*xs[s1*132+cA];
                    float v11=(acc2[mb][2*j][3]+bA1)*xs[s1*132+cA+1];
                    float w00=(acc2[mb][2*j+1][0]+bB0)*xs[s0*132+cB];
                    float w01=(acc2[mb][2*j+1][1]+bB1)*xs[s0*132+cB+1];
                    float w10=(acc2[mb][2*j+1][2]+bB0)*xs[s1*132+cB];
                    float w11=(acc2[mb][2*j+1][3]+bB1)*xs[s1*132+cB+1];
                    if(s0!=d0){
                        atomicAdd(&sagg[d0*132+cA],   v00); atomicAdd(&sagg[d0*132+cA+1], v01);
                        atomicAdd(&sagg[d0*132+cB],   w00); atomicAdd(&sagg[d0*132+cB+1], w01);
                    }
                    if(s1!=d1){
                        atomicAdd(&sagg[d1*132+cA],   v10); atomicAdd(&sagg[d1*132+cA+1], v11);
                        atomicAdd(&sagg[d1*132+cB],   w10); atomicAdd(&sagg[d1*132+cB+1], w11);
                    }
                    u32 h4[4],l4[4];
                    sp2(v00,v01,h4[0],l4[0]); sp2(v10,v11,h4[1],l4[1]);
                    sp2(w00,w01,h4[2],l4[2]); sp2(w10,w11,h4[3],l4[3]);
                    u32* c = base + (hf*4+j)*512 + mb*128;
                    *(uint4*)(c+lane*4)     = make_uint4(h4[0],h4[1],h4[2],h4[3]);
                    *(uint4*)(c+256+lane*4) = make_uint4(l4[0],l4[1],l4[2],l4[3]);
                }
            }
        }
    }
    __syncthreads();
    for (int i=tid;i<Aat*128;i+=288)
        g_agg[(size_t)m*3072 + i] = sagg[(i>>7)*132 + (i&127)];
}

__global__ void __launch_bounds__(256,1) k_node_mma(const float* __restrict__ nb1, const float* __restrict__ nb2){
    extern __shared__ __align__(16) char sm[];
    char *W1h = sm, *W1l = sm+IMG, *W2h = sm+2*IMG, *W2l = sm+3*IMG;
    char *Ah = sm+4*IMG, *Al = sm+5*IMG;
    float* b1s = (float*)(sm + 6*IMG); float* b2s = b1s + 128;
    const int tid = threadIdx.x, wid = tid>>5, lane = tid&31, R = wid*16;
    for (int i = tid; i < 2048; i += 256){
        int k = i>>4, ch = i&15; u32 d = k*PIT + ch*16;
        cpa16(smaddr(W1h)+d, g_Wimg[3][0]+i*16);
        cpa16(smaddr(W1l)+d, g_Wimg[3][1]+i*16);
        cpa16(smaddr(W2h)+d, g_Wimg[4][0]+i*16);
        cpa16(smaddr(W2l)+d, g_Wimg[4][1]+i*16);
    }
    CP_COMMIT;
    if (tid < 128){ b1s[tid] = nb1[tid]; b2s[tid] = nb2[tid]; }
    CP_WAIT0; __syncthreads();
    size_t rowbase = (size_t)blockIdx.x * 128;
    stage_band(g_agg + rowbase*128, Ah, Al, R, lane);
    __syncwarp();
    float acc[16][4]; zacc16(acc);
    wgemm3(acc, smaddr(Ah)+R*PIT, smaddr(Al)+R*PIT, smaddr(W1h), smaddr(W1l), lane);
    write_mid(acc, b1s, Ah, Al, R, lane);
    __syncwarp();
    zacc16(acc);
    wgemm3(acc, smaddr(Ah)+R*PIT, smaddr(Al)+R*PIT, smaddr(W2h), smaddr(W2l), lane);
    int r0 = (int)rowbase + R + (lane>>2), cb = (lane&3)*2;
    #pragma unroll
    for (int nb = 0; nb < 16; ++nb){
        int c = nb*8 + cb;
        float bx = b2s[c], by = b2s[c+1];
        float2 h0 = *(float2*)(g_h + (size_t)r0*128 + c);
        float2 h1 = *(float2*)(g_h + (size_t)(r0+8)*128 + c);
        h0.x += acc[nb][0] + bx;  h0.y += acc[nb][1] + by;
        h1.x += acc[nb][2] + bx;  h1.y += acc[nb][3] + by;
        *(float2*)(g_h + (size_t)r0*128 + c)     = h0;
        *(float2*)(g_h + (size_t)(r0+8)*128 + c) = h1;
    }
}

__global__ void __launch_bounds__(256) k_graph(const float* __restrict__ gw1, const float* __restrict__ gb1,
                                               const float* __restrict__ gw2, const float* __restrict__ gb2,
                                               float* __restrict__ out)
{
    __shared__ float hs[Aat*128];
    __shared__ float w1s[128*64];
    __shared__ float red[256];
    const int tid = threadIdx.x, m = blockIdx.x;
    {
        const float4* hg = (const float4*)(g_h + (size_t)m*Aat*128);
        for (int i = tid; i < 768; i += 256) ((float4*)hs)[i] = hg[i];
        const float4* wg = (const float4*)gw1;
        for (int i = tid; i < 2048; i += 256) ((float4*)w1s)[i] = wg[i];
    }
    __syncthreads();
    float local = 0.f;
    for (int pos = tid; pos < Aat*64; pos += 256){
        int s = pos >> 6, c = pos & 63;
        float acc = gb1[c];
        #pragma unroll 16
        for (int k = 0; k < 128; ++k) acc += hs[s*128+k] * w1s[k*64+c];
        local += ssp(acc) * gw2[c];
    }
    red[tid] = local;
    __syncthreads();
    #pragma unroll
    for (int off = 128; off > 0; off >>= 1){
        if (tid < off) red[tid] += red[tid+off];
        __syncthreads();
    }
    if (tid == 0) out[m] = red[0] + (float)Aat * gb2[0];
}

extern "C" void kernel_launch(void* const* d_in, const int* in_sizes, int n_in,
                              void* d_out, int out_size)
{
    const int*   charges = (const int*)  d_in[0];
    const float* coords  = (const float*)d_in[1];
    const float* emb = (const float*)d_in[4];
    const float* nlw = (const float*)d_in[5];
    const float* ew1 = (const float*)d_in[6];
    const float* eb1 = (const float*)d_in[7];
    const float* ew2 = (const float*)d_in[8];
    const float* eb2 = (const float*)d_in[9];
    const float* nw1 = (const float*)d_in[10];
    const float* nb1 = (const float*)d_in[11];
    const float* nw2 = (const float*)d_in[12];
    const float* nb2 = (const float*)d_in[13];
    const float* gw1 = (const float*)d_in[14];
    const float* gb1 = (const float*)d_in[15];
    const float* gw2 = (const float*)d_in[16];
    const float* gb2 = (const float*)d_in[17];
    float* out = (float*)d_out;

    const int SME = 4*IMG + (24*132*2 + 256)*4;   // 165632
    const int SMN = 6*IMG + 1024;                 // 209920
    const int SMX = 4*IMG;                        // 139264
    cudaFuncSetAttribute(k_edge,     cudaFuncAttributeMaxDynamicSharedMemorySize, SME);
    cudaFuncSetAttribute(k_node_mma, cudaFuncAttributeMaxDynamicSharedMemorySize, SMN);
    cudaFuncSetAttribute(k_x_mma,    cudaFuncAttributeMaxDynamicSharedMemorySize, SMX);

    k_init   <<<5 + (Nnode*128)/256, 256>>>(charges, emb, nlw, ew1, ew2, nw1, nw2);
    k_init_ea<<<(Mmol*18)/8, 256>>>(coords);

    for (int l = 0; l < 4; ++l) {
        k_x_mma   <<<384,  256, SMX>>>();
        k_edge    <<<Mmol, 288, SME>>>(eb1, eb2);
        k_node_mma<<<384,  256, SMN>>>(nb1, nb2);
    }
    k_graph<<<Mmol, 256>>>(gw1, gb1, gw2, gb2, out);
}

// round 9
// speedup vs baseline: 2.6986x; 2.2496x over previous
#include <cuda_runtime.h>
#include <cuda_bf16.h>

typedef unsigned int u32; typedef unsigned long long u64;
#define Mmol 2048
#define Aat 24
#define PIT 272
#define IMG 34816

// EA fragments per (m,d): 8 ks-chunks of 512 u32 [hi mb0|hi mb1|lo mb0|lo mb1]
__device__ u32 g_EAf[(size_t)Mmol*24*4096];
__device__ __align__(16) unsigned char g_Wimg[5][2][32768]; // [nlw,ew1,ew2,nw1,nw2][hi,lo]

__device__ __forceinline__ u32 smaddr(const void* p){
    u32 a; asm("{ .reg .u64 t; cvta.to.shared.u64 t, %1; cvt.u32.u64 %0, t; }" : "=r"(a) : "l"(p)); return a;
}
__device__ __forceinline__ float ssp(float x){
    return fmaxf(x, 0.f) + __logf(1.f + __expf(-fabsf(x))) - 0.6931471805599453f;
}
__device__ __forceinline__ void cpa16(u32 dst, const void* src){
    asm volatile("cp.async.cg.shared.global [%0], [%1], 16;" :: "r"(dst), "l"(src) : "memory");
}
#define CP_COMMIT asm volatile("cp.async.commit_group;" ::: "memory")
#define CP_WAIT0  asm volatile("cp.async.wait_group 0;"  ::: "memory")
__device__ __forceinline__ void ldsm4t(u32* r, u32 a){
    asm volatile("ldmatrix.sync.aligned.m8n8.x4.trans.shared.b16 {%0,%1,%2,%3}, [%4];"
        : "=r"(r[0]),"=r"(r[1]),"=r"(r[2]),"=r"(r[3]) : "r"(a));
}
__device__ __forceinline__ void mma_bf(float* d, const u32* a, u32 b0, u32 b1){
    asm volatile("mma.sync.aligned.m16n8k16.row.col.f32.bf16.bf16.f32 "
        "{%0,%1,%2,%3}, {%4,%5,%6,%7}, {%8,%9}, {%0,%1,%2,%3};"
        : "+f"(d[0]),"+f"(d[1]),"+f"(d[2]),"+f"(d[3])
        : "r"(a[0]),"r"(a[1]),"r"(a[2]),"r"(a[3]),"r"(b0),"r"(b1));
}
__device__ __forceinline__ void sp2(float x, float y, u32& h, u32& l){
    __nv_bfloat162 hb = __floats2bfloat162_rn(x, y);
    __nv_bfloat162 lb = __floats2bfloat162_rn(x - __bfloat162float(hb.x), y - __bfloat162float(hb.y));
    h = *(u32*)&hb; l = *(u32*)&lb;
}

// weight-image prep (unchanged)
__global__ void k_init(const float* nlw, const float* ew1, const float* ew2,
                       const float* nw1, const float* nw2){
    const float* srcs[5] = {nlw, ew1, ew2, nw1, nw2};
    const float* src = srcs[blockIdx.x];
    int n = threadIdx.x;
    for (int k = 0; k < 128; ++k){
        float v = src[k*128 + n];
        __nv_bfloat16 h = __float2bfloat16_rn(v);
        __nv_bfloat16 l = __float2bfloat16_rn(v - __bfloat162float(h));
        *(__nv_bfloat16*)(g_Wimg[blockIdx.x][0] + k*256 + n*2) = h;
        *(__nv_bfloat16*)(g_Wimg[blockIdx.x][1] + k*256 + n*2) = l;
    }
}

// M=32 x N=128 GEMM, A(fp32, smem, stride 132, rows<24 real) * B(image pair), 3-term.
// warp w: mb=w&1, cg=w>>1. acc[4][4] covers 4 n8-blocks at cols blk16*16 + (jb&1)*8.
__device__ __forceinline__ void gemm_sm(const float* abuf, u32 bhi, u32 bli,
                                        int mb, int cg, int lane, u32 loff, float acc[4][4]){
    const int q = lane>>2, cp = lane&3;
    const int r0 = mb*16 + q, r1 = r0 + 8;
    const bool ok1 = (r1 < 24);
    #pragma unroll
    for (int ks=0; ks<8; ++ks){
        int kc = 16*ks + 2*cp;
        float2 v0 = *(const float2*)&abuf[r0*132+kc];
        float2 v1 = ok1 ? *(const float2*)&abuf[r1*132+kc] : make_float2(0.f,0.f);
        float2 v2 = *(const float2*)&abuf[r0*132+kc+8];
        float2 v3 = ok1 ? *(const float2*)&abuf[r1*132+kc+8] : make_float2(0.f,0.f);
        u32 ah[4], al[4];
        sp2(v0.x,v0.y,ah[0],al[0]); sp2(v1.x,v1.y,ah[1],al[1]);
        sp2(v2.x,v2.y,ah[2],al[2]); sp2(v3.x,v3.y,ah[3],al[3]);
        #pragma unroll
        for (int j=0;j<2;++j){
            u32 bh[4],bl[4]; u32 ba = loff + ks*(16*PIT) + (cg*2+j)*32;
            ldsm4t(bh, bhi+ba); ldsm4t(bl, bli+ba);
            mma_bf(acc[2*j],   ah, bh[0], bh[1]);
            mma_bf(acc[2*j],   ah, bl[0], bl[1]);
            mma_bf(acc[2*j],   al, bh[0], bh[1]);
            mma_bf(acc[2*j+1], ah, bh[2], bh[3]);
            mma_bf(acc[2*j+1], ah, bl[2], bl[3]);
            mma_bf(acc[2*j+1], al, bh[2], bh[3]);
        }
    }
}

__global__ void __launch_bounds__(256,1) k_fused(
    const int* __restrict__ charges, const float* __restrict__ coords,
    const float* __restrict__ emb,
    const float* __restrict__ eb1, const float* __restrict__ eb2,
    const float* __restrict__ nb1, const float* __restrict__ nb2,
    const float* __restrict__ gw1, const float* __restrict__ gb1,
    const float* __restrict__ gw2, const float* __restrict__ gb2,
    float* __restrict__ out)
{
    extern __shared__ __align__(16) char sm[];
    char *WAh = sm, *WAl = sm+IMG, *WBh = sm+2*IMG, *WBl = sm+3*IMG;
    float* hs   = (float*)(sm + 4*IMG);   // 24x132
    float* xs   = hs + 24*132;            // 32x132 (rows 24-31 stay zero)
    float* sagg = xs + 32*132;            // 24x132
    float* bb   = sagg + 24*132;          // 512: eb1|eb2|nb1|nb2
    const int tid = threadIdx.x, m = blockIdx.x;
    const int wid = tid>>5, lane = tid&31, q = lane>>2, cp = lane&3;
    const u32 loff = (lane&15)*PIT + (lane>>4)*16;
    const u32 sAh = smaddr(WAh), sAl = smaddr(WAl), sBh = smaddr(WBh), sBl = smaddr(WBl);
    const int mb = wid & 1, cg = wid >> 1;

    // ---- init: h, biases, xs pad rows ----
    for (int i = tid; i < Aat*128; i += 256)
        hs[(i>>7)*132 + (i&127)] = emb[charges[m*Aat + (i>>7)]*128 + (i&127)];
    for (int i = tid; i < 8*132; i += 256) xs[24*132 + i] = 0.f;
    if (tid < 128){ bb[tid]=eb1[tid]; bb[128+tid]=eb2[tid]; bb[256+tid]=nb1[tid]; bb[384+tid]=nb2[tid]; }

    // ---- RBF -> EA fragments (3 d's per warp) ----
    {
        const float* cm = coords + (size_t)m*72;
        for (int i3 = 0; i3 < 3; ++i3){
            int d = wid + 8*i3;
            float ddx=cm[d*3], ddy=cm[d*3+1], ddz=cm[d*3+2];
            float dv[3];
            #pragma unroll
            for (int i=0;i<3;++i){
                int s = q + i*8;
                float ax=cm[s*3]-ddx, ay=cm[s*3+1]-ddy, az=cm[s*3+2]-ddz;
                dv[i] = sqrtf(ax*ax+ay*ay+az*az);
            }
            const float delta = 10.f/127.f, coeff = -0.5f/(delta*delta);
            u32* base = g_EAf + ((size_t)(m*24+d))*4096;
            #pragma unroll
            for (int ks=0; ks<8; ++ks){
                float c0 = (float)(16*ks + 2*cp);
                float v[3][4];
                #pragma unroll
                for (int i=0;i<3;++i)
                    #pragma unroll
                    for (int j=0;j<4;++j){
                        float od = dv[i] - delta*(c0 + (float)((j>>1)*8 + (j&1)));
                        v[i][j] = (fabsf(od) < 1.2f) ? __expf(coeff*od*od) : 0.f;
                    }
                u32 h[4],l[4],h2[4],l2[4];
                sp2(v[0][0],v[0][1],h[0],l[0]);  sp2(v[1][0],v[1][1],h[1],l[1]);
                sp2(v[0][2],v[0][3],h[2],l[2]);  sp2(v[1][2],v[1][3],h[3],l[3]);
                sp2(v[2][0],v[2][1],h2[0],l2[0]); h2[1]=0; l2[1]=0;
                sp2(v[2][2],v[2][3],h2[2],l2[2]); h2[3]=0; l2[3]=0;
                u32* c = base + ks*512;
                *(uint4*)(c + lane*4)       = make_uint4(h[0],h[1],h[2],h[3]);
                *(uint4*)(c + 128 + lane*4) = make_uint4(h2[0],h2[1],h2[2],h2[3]);
                *(uint4*)(c + 256 + lane*4) = make_uint4(l[0],l[1],l[2],l[3]);
                *(uint4*)(c + 384 + lane*4) = make_uint4(l2[0],l2[1],l2[2],l2[3]);
            }
        }
    }

    const float* b1s = bb;        // edge biases
    const float* b2s = bb + 128;

    for (int layer = 0; layer < 4; ++layer){
        // ===== x = h @ nlw =====
        for (int i=tid;i<2048;i+=256){
            int k=i>>4, ch=i&15; u32 dof=k*PIT+ch*16;
            cpa16(sAh+dof, g_Wimg[0][0]+i*16); cpa16(sAl+dof, g_Wimg[0][1]+i*16);
        }
        CP_COMMIT; CP_WAIT0; __syncthreads();
        {
            float acc[4][4];
            #pragma unroll
            for (int i=0;i<4;++i){acc[i][0]=0;acc[i][1]=0;acc[i][2]=0;acc[i][3]=0;}
            gemm_sm(hs, sAh, sAl, mb, cg, lane, loff, acc);
            int r0 = mb*16+q, r1 = r0+8;
            #pragma unroll
            for (int jb=0;jb<4;++jb){
                int c = (cg*2+(jb>>1))*16 + (jb&1)*8 + 2*cp;
                *(float2*)&xs[r0*132+c] = make_float2(acc[jb][0], acc[jb][1]);
                if (r1 < 24) *(float2*)&xs[r1*132+c] = make_float2(acc[jb][2], acc[jb][3]);
            }
        }
        __syncthreads();
        // ===== edge phase (R6 body) =====
        for (int i=tid;i<2048;i+=256){
            int k=i>>4, ch=i&15; u32 dof=k*PIT+ch*16;
            cpa16(sAh+dof, g_Wimg[1][0]+i*16); cpa16(sAl+dof, g_Wimg[1][1]+i*16);
            cpa16(sBh+dof, g_Wimg[2][0]+i*16); cpa16(sBl+dof, g_Wimg[2][1]+i*16);
        }
        CP_COMMIT; CP_WAIT0; __syncthreads();
        for (int pass=0; pass<3; ++pass){
            const int d = pass*8 + wid;
            u32* base = g_EAf + ((size_t)(m*24+d))*4096;
            float acc1[2][16][4];
            #pragma unroll
            for (int mb2=0;mb2<2;++mb2)
                #pragma unroll
                for (int i=0;i<16;++i){acc1[mb2][i][0]=0;acc1[mb2][i][1]=0;acc1[mb2][i][2]=0;acc1[mb2][i][3]=0;}
            uint4 H0=*(const uint4*)(base+lane*4),     H1=*(const uint4*)(base+128+lane*4);
            uint4 L0=*(const uint4*)(base+256+lane*4), L1=*(const uint4*)(base+384+lane*4);
            #pragma unroll
            for (int ks=0;ks<8;++ks){
                uint4 nH0,nH1,nL0,nL1;
                if (ks<7){
                    const u32* nb = base+(ks+1)*512;
                    nH0=*(const uint4*)(nb+lane*4);     nH1=*(const uint4*)(nb+128+lane*4);
                    nL0=*(const uint4*)(nb+256+lane*4); nL1=*(const uint4*)(nb+384+lane*4);
                }
                u32 ah0[4]={H0.x,H0.y,H0.z,H0.w}, ah1[4]={H1.x,H1.y,H1.z,H1.w};
                u32 al0[4]={L0.x,L0.y,L0.z,L0.w}, al1[4]={L1.x,L1.y,L1.z,L1.w};
                #pragma unroll
                for (int j=0;j<8;++j){
                    u32 bh[4],bl[4]; u32 ba=loff+ks*(16*PIT)+j*32;
                    ldsm4t(bh,sAh+ba); ldsm4t(bl,sAl+ba);
                    mma_bf(acc1[0][2*j],   ah0,bh[0],bh[1]); mma_bf(acc1[0][2*j],   ah0,bl[0],bl[1]); mma_bf(acc1[0][2*j],   al0,bh[0],bh[1]);
                    mma_bf(acc1[0][2*j+1], ah0,bh[2],bh[3]); mma_bf(acc1[0][2*j+1], ah0,bl[2],bl[3]); mma_bf(acc1[0][2*j+1], al0,bh[2],bh[3]);
                    mma_bf(acc1[1][2*j],   ah1,bh[0],bh[1]); mma_bf(acc1[1][2*j],   ah1,bl[0],bl[1]); mma_bf(acc1[1][2*j],   al1,bh[0],bh[1]);
                    mma_bf(acc1[1][2*j+1], ah1,bh[2],bh[3]); mma_bf(acc1[1][2*j+1], ah1,bl[2],bl[3]); mma_bf(acc1[1][2*j+1], al1,bh[2],bh[3]);
                }
                if (ks<7){ H0=nH0; H1=nH1; L0=nL0; L1=nL1; }
            }
            u32 a2h[2][8][4], a2l[2][8][4];
            #pragma unroll
            for (int mb2=0;mb2<2;++mb2)
                #pragma unroll
                for (int j=0;j<8;++j){
                    int c0=16*j+2*cp;
                    float bA0=b1s[c0], bA1=b1s[c0+1], bB0=b1s[c0+8], bB1=b1s[c0+9];
                    sp2(ssp(acc1[mb2][2*j][0]+bA0),   ssp(acc1[mb2][2*j][1]+bA1),   a2h[mb2][j][0], a2l[mb2][j][0]);
                    sp2(ssp(acc1[mb2][2*j][2]+bA0),   ssp(acc1[mb2][2*j][3]+bA1),   a2h[mb2][j][1], a2l[mb2][j][1]);
                    sp2(ssp(acc1[mb2][2*j+1][0]+bB0), ssp(acc1[mb2][2*j+1][1]+bB1), a2h[mb2][j][2], a2l[mb2][j][2]);
                    sp2(ssp(acc1[mb2][2*j+1][2]+bB0), ssp(acc1[mb2][2*j+1][3]+bB1), a2h[mb2][j][3], a2l[mb2][j][3]);
                }
            #pragma unroll
            for (int hf=0; hf<2; ++hf){
                float acc2[2][8][4];
                #pragma unroll
                for (int mb2=0;mb2<2;++mb2)
                    #pragma unroll
                    for (int i=0;i<8;++i){acc2[mb2][i][0]=0;acc2[mb2][i][1]=0;acc2[mb2][i][2]=0;acc2[mb2][i][3]=0;}
                #pragma unroll
                for (int ks=0;ks<8;++ks)
                    #pragma unroll
                    for (int j=0;j<4;++j){
                        u32 bh[4],bl[4]; u32 ba=loff+ks*(16*PIT)+(hf*4+j)*32;
                        ldsm4t(bh,sBh+ba); ldsm4t(bl,sBl+ba);
                        #pragma unroll
                        for (int mb2=0;mb2<2;++mb2){
                            mma_bf(acc2[mb2][2*j],   a2h[mb2][ks],bh[0],bh[1]);
                            mma_bf(acc2[mb2][2*j],   a2h[mb2][ks],bl[0],bl[1]);
                            mma_bf(acc2[mb2][2*j],   a2l[mb2][ks],bh[0],bh[1]);
                            mma_bf(acc2[mb2][2*j+1], a2h[mb2][ks],bh[2],bh[3]);
                            mma_bf(acc2[mb2][2*j+1], a2h[mb2][ks],bl[2],bl[3]);
                            mma_bf(acc2[mb2][2*j+1], a2l[mb2][ks],bh[2],bh[3]);
                        }
                    }
                float wag[4][4];
                #pragma unroll
                for (int j=0;j<4;++j){wag[j][0]=0;wag[j][1]=0;wag[j][2]=0;wag[j][3]=0;}
                #pragma unroll
                for (int mb2=0;mb2<2;++mb2){
                    int s0=mb2*16+q, s1=s0+8;
                    bool k0=(s0<24)&&(s0!=d), k1=(s1<24)&&(s1!=d);
                    #pragma unroll
                    for (int j=0;j<4;++j){
                        int cA=hf*64+16*j+2*cp, cB=cA+8;
                        float bA0=b2s[cA],bA1=b2s[cA+1],bB0=b2s[cB],bB1=b2s[cB+1];
                        float v00=(acc2[mb2][2*j][0]+bA0)*xs[s0*132+cA];
                        float v01=(acc2[mb2][2*j][1]+bA1)*xs[s0*132+cA+1];
                        float v10=(acc2[mb2][2*j][2]+bA0)*xs[s1*132+cA];
                        float v11=(acc2[mb2][2*j][3]+bA1)*xs[s1*132+cA+1];
                        float w00=(acc2[mb2][2*j+1][0]+bB0)*xs[s0*132+cB];
                        float w01=(acc2[mb2][2*j+1][1]+bB1)*xs[s0*132+cB+1];
                        float w10=(acc2[mb2][2*j+1][2]+bB0)*xs[s1*132+cB];
                        float w11=(acc2[mb2][2*j+1][3]+bB1)*xs[s1*132+cB+1];
                        if(k0){ wag[j][0]+=v00; wag[j][1]+=v01; wag[j][2]+=w00; wag[j][3]+=w01; }
                        if(k1){ wag[j][0]+=v10; wag[j][1]+=v11; wag[j][2]+=w10; wag[j][3]+=w11; }
                        u32 h4[4],l4[4];
                        sp2(v00,v01,h4[0],l4[0]); sp2(v10,v11,h4[1],l4[1]);
                        sp2(w00,w01,h4[2],l4[2]); sp2(w10,w11,h4[3],l4[3]);
                        u32* c = base + (hf*4+j)*512 + mb2*128;
                        *(uint4*)(c+lane*4)     = make_uint4(h4[0],h4[1],h4[2],h4[3]);
                        *(uint4*)(c+256+lane*4) = make_uint4(l4[0],l4[1],l4[2],l4[3]);
                    }
                }
                #pragma unroll
                for (int j=0;j<4;++j){
                    #pragma unroll
                    for (int u2=0;u2<4;++u2){
                        float tt=wag[j][u2];
                        tt += __shfl_xor_sync(~0u,tt,4); tt += __shfl_xor_sync(~0u,tt,8); tt += __shfl_xor_sync(~0u,tt,16);
                        wag[j][u2]=tt;
                    }
                    if (lane<4){
                        int cA=hf*64+16*j+2*lane;
                        *(float2*)&sagg[d*132+cA]   = make_float2(wag[j][0],wag[j][1]);
                        *(float2*)&sagg[d*132+cA+8] = make_float2(wag[j][2],wag[j][3]);
                    }
                }
            }
        }
        __syncthreads();
        // ===== node phase =====
        for (int i=tid;i<2048;i+=256){
            int k=i>>4, ch=i&15; u32 dof=k*PIT+ch*16;
            cpa16(sAh+dof, g_Wimg[3][0]+i*16); cpa16(sAl+dof, g_Wimg[3][1]+i*16);
            cpa16(sBh+dof, g_Wimg[4][0]+i*16); cpa16(sBl+dof, g_Wimg[4][1]+i*16);
        }
        CP_COMMIT; CP_WAIT0; __syncthreads();
        {
            float acc[4][4];
            #pragma unroll
            for (int i=0;i<4;++i){acc[i][0]=0;acc[i][1]=0;acc[i][2]=0;acc[i][3]=0;}
            gemm_sm(sagg, sAh, sAl, mb, cg, lane, loff, acc);
            int r0 = mb*16+q, r1 = r0+8;
            #pragma unroll
            for (int jb=0;jb<4;++jb){
                int c = (cg*2+(jb>>1))*16 + (jb&1)*8 + 2*cp;
                float b0v = bb[256+c], b1v = bb[256+c+1];
                *(float2*)&xs[r0*132+c] = make_float2(ssp(acc[jb][0]+b0v), ssp(acc[jb][1]+b1v));
                if (r1 < 24) *(float2*)&xs[r1*132+c] = make_float2(ssp(acc[jb][2]+b0v), ssp(acc[jb][3]+b1v));
            }
        }
        __syncthreads();
        {
            float acc[4][4];
            #pragma unroll
            for (int i=0;i<4;++i){acc[i][0]=0;acc[i][1]=0;acc[i][2]=0;acc[i][3]=0;}
            gemm_sm(xs, sBh, sBl, mb, cg, lane, loff, acc);
            int r0 = mb*16+q, r1 = r0+8;
            #pragma unroll
            for (int jb=0;jb<4;++jb){
                int c = (cg*2+(jb>>1))*16 + (jb&1)*8 + 2*cp;
                float b0v = bb[384+c], b1v = bb[384+c+1];
                float2 h0 = *(float2*)&hs[r0*132+c];
                h0.x += acc[jb][0]+b0v; h0.y += acc[jb][1]+b1v;
                *(float2*)&hs[r0*132+c] = h0;
                if (r1 < 24){
                    float2 h1 = *(float2*)&hs[r1*132+c];
                    h1.x += acc[jb][2]+b0v; h1.y += acc[jb][3]+b1v;
                    *(float2*)&hs[r1*132+c] = h1;
                }
            }
        }
        __syncthreads();
        // zero xs pad rows again (mid overwrote rows 0-23 only; pads still 0, but keep invariant cheap)
    }

    // ===== graph readout =====
    float* w1s = (float*)WAh;          // 128x64 floats
    for (int i=tid;i<2048;i+=256) ((float4*)w1s)[i] = ((const float4*)gw1)[i];
    __syncthreads();
    float local = 0.f;
    for (int pos = tid; pos < Aat*64; pos += 256){
        int s = pos >> 6, c = pos & 63;
        float acc = gb1[c];
        #pragma unroll 16
        for (int k = 0; k < 128; ++k) acc += hs[s*132+k] * w1s[k*64+c];
        local += ssp(acc) * gw2[c];
    }
    float* red = sagg;
    red[tid] = local;
    __syncthreads();
    #pragma unroll
    for (int off = 128; off > 0; off >>= 1){
        if (tid < off) red[tid] += red[tid+off];
        __syncthreads();
    }
    if (tid == 0) out[m] = red[0] + (float)Aat * gb2[0];
}

extern "C" void kernel_launch(void* const* d_in, const int* in_sizes, int n_in,
                              void* d_out, int out_size)
{
    const int*   charges = (const int*)  d_in[0];
    const float* coords  = (const float*)d_in[1];
    const float* emb = (const float*)d_in[4];
    const float* nlw = (const float*)d_in[5];
    const float* ew1 = (const float*)d_in[6];
    const float* eb1 = (const float*)d_in[7];
    const float* ew2 = (const float*)d_in[8];
    const float* eb2 = (const float*)d_in[9];
    const float* nw1 = (const float*)d_in[10];
    const float* nb1 = (const float*)d_in[11];
    const float* nw2 = (const float*)d_in[12];
    const float* nb2 = (const float*)d_in[13];
    const float* gw1 = (const float*)d_in[14];
    const float* gb1 = (const float*)d_in[15];
    const float* gw2 = (const float*)d_in[16];
    const float* gb2 = (const float*)d_in[17];
    float* out = (float*)d_out;

    const int SMF = 4*IMG + (24*132 + 32*132 + 24*132 + 512)*4;  // 183552
    cudaFuncSetAttribute(k_fused, cudaFuncAttributeMaxDynamicSharedMemorySize, SMF);

    k_init <<<5, 128>>>(nlw, ew1, ew2, nw1, nw2);
    k_fused<<<Mmol, 256, SMF>>>(charges, coords, emb, eb1, eb2, nb1, nb2,
                                gw1, gb1, gw2, gb2, out);
}